// round 10
// baseline (speedup 1.0000x reference)
#include <cuda_runtime.h>

#define BDIM 128
#define HDIM 32
#define SDIM 64
#define DDIM 128
#define STARTLEN 32
#define NT 256
#define BSTR (HDIM * SDIM * DDIM)

// SMEM (floats): Vs[2][64][128]=16384, cur[2][128]=256, red[21][128]=2688
// RED rows 0-19: P1 partials (q slots 0-2, k slots 3-6, v slots 7-9; row = slot*2+batch)
// RED row 20: raw attention scores att[2][64]
#define VS   0
#define CUR  16384
#define RED  16640
#define ATT  (RED + 20 * DDIM)
#define SMEM_FLOATS 19328            // 77312 B -> 3 CTAs/SM (231936 B)

// Fused weights per head: [h][384][128]  (Wo@Wq | Wo@Wk | Wo@Wv)
__device__ float g_comb[HDIM * 3 * DDIM * DDIM];

// ---------------- fuse kernel: C = Wo @ Wm, 384 CTAs, 32-row panels ----------------
__global__ void __launch_bounds__(256)
fuse_weights_kernel(const float* __restrict__ wq, const float* __restrict__ wk,
                    const float* __restrict__ wv, const float* __restrict__ wo)
{
    __shared__ float Ws[DDIM * DDIM];
    __shared__ float Wop[32 * DDIM];
    const int h    = blockIdx.x / 12;
    const int rem  = blockIdx.x % 12;
    const int m    = rem >> 2;
    const int d0   = (rem & 3) << 5;
    const int t    = threadIdx.x;

    const float* Wm = ((m == 0) ? wq : ((m == 1) ? wk : wv)) + (size_t)h * DDIM * DDIM;
    const float* Wo = wo + (size_t)h * DDIM * DDIM;

    for (int i = t; i < DDIM * DDIM / 4; i += 256)
        ((float4*)Ws)[i] = ((const float4*)Wm)[i];
    for (int i = t; i < 32 * DDIM / 4; i += 256)
        ((float4*)Wop)[i] = ((const float4*)(Wo + d0 * DDIM))[i];
    __syncthreads();

    const int c = t & 15;
    const int r = t >> 4;
    float acc[2][8];
    #pragma unroll
    for (int i = 0; i < 2; ++i)
        #pragma unroll
        for (int j = 0; j < 8; ++j) acc[i][j] = 0.f;

    #pragma unroll 4
    for (int e = 0; e < DDIM; ++e) {
        float4 wm0 = *(const float4*)&Ws[e * DDIM + c * 8];
        float4 wm1 = *(const float4*)&Ws[e * DDIM + c * 8 + 4];
        #pragma unroll
        for (int i = 0; i < 2; ++i) {
            float wo_v = Wop[(r * 2 + i) * DDIM + e];
            acc[i][0] += wo_v * wm0.x; acc[i][1] += wo_v * wm0.y;
            acc[i][2] += wo_v * wm0.z; acc[i][3] += wo_v * wm0.w;
            acc[i][4] += wo_v * wm1.x; acc[i][5] += wo_v * wm1.y;
            acc[i][6] += wo_v * wm1.z; acc[i][7] += wo_v * wm1.w;
        }
    }

    float* dst = g_comb + ((size_t)h * 384 + m * DDIM + d0) * DDIM;
    #pragma unroll
    for (int i = 0; i < 2; ++i) {
        *(float4*)&dst[(r * 2 + i) * DDIM + c * 8]     = make_float4(acc[i][0], acc[i][1], acc[i][2], acc[i][3]);
        *(float4*)&dst[(r * 2 + i) * DDIM + c * 8 + 4] = make_float4(acc[i][4], acc[i][5], acc[i][6], acc[i][7]);
    }
}

// ---------------- decode kernel ----------------
__global__ void __launch_bounds__(NT, 3)
attn_decode_kernel(const float* __restrict__ x_in,
                   const float* __restrict__ k_in,
                   const float* __restrict__ v_in,
                   const float* __restrict__ wq,
                   const float* __restrict__ wk,
                   const float* __restrict__ wv,
                   const float* __restrict__ wo,
                   float* k_out, float* v_out, float* __restrict__ x_out)
{
    extern __shared__ float sm[];

    const int t = threadIdx.x;
    const int w = t >> 5;
    const int l = t & 31;
    const int h  = blockIdx.x >> 6;
    const int b0 = (blockIdx.x & 63) << 1;

    float* kg = k_out + (size_t)(b0 * HDIM + h) * (SDIM * DDIM);
    float* vg = v_out + (size_t)(b0 * HDIM + h) * (SDIM * DDIM);

    // ---- prologue: k_in -> k_out (global cache), v_in -> smem + v_out, x -> cur ----
    for (int b = 0; b < 2; ++b) {
        const float4* kin = (const float4*)(k_in + (size_t)((b0 + b) * HDIM + h) * (SDIM * DDIM));
        const float4* vin = (const float4*)(v_in + (size_t)((b0 + b) * HDIM + h) * (SDIM * DDIM));
        float4* kd = (float4*)(kg + (size_t)b * BSTR);
        float4* vd = (float4*)(vg + (size_t)b * BSTR);
        for (int i = t; i < SDIM * DDIM / 4; i += NT) {
            kd[i] = kin[i];
            float4 vv = vin[i];
            *(float4*)&sm[VS + b * 8192 + 4 * i] = vv;
            vd[i] = vv;
        }
        const float* xin = x_in + (size_t)((b0 + b) * HDIM + h) * DDIM;
        for (int d = t; d < DDIM; d += NT) sm[CUR + b * DDIM + d] = xin[d];
    }
    __syncthreads();

    // P1 flat split: 384 rows (q|k|v), warp w -> rows [48w, 48w+48)
    const int r0  = w * 48;
    const int mA  = r0 >> 7;
    const int dA  = r0 & 127;
    const int nA  = min(48, 128 - dA);
    const int nB  = 48 - nA;
    const int extra = (w > 2) + (w > 5);
    const int slotA = w + extra;
    const int slotB = slotA + 1;

    const float* origM[3] = { wq + (size_t)h * DDIM * DDIM,
                              wk + (size_t)h * DDIM * DDIM,
                              wv + (size_t)h * DDIM * DDIM };
    const float* Ch = g_comb + (size_t)h * 384 * DDIM;

    const float4* origA4  = (const float4*)(origM[mA] + (size_t)dA * DDIM);
    const float4* fusedA4 = (const float4*)(Ch + (size_t)r0 * DDIM);
    const float4* origB4  = (nB > 0) ? (const float4*)origM[mA + 1] : nullptr;
    const float4* fusedB4 = (const float4*)(Ch + (size_t)(r0 + nA) * DDIM);

    const int p2b = w >> 2, p2s0 = (w & 3) << 4;     // P2: (batch, s-quarter)
    const int p4b = t >> 7, p4d = t & 127;           // P4: (batch, d)

    for (int gen = STARTLEN; gen < SDIM; ++gen) {
        const bool first = (gen == STARTLEN);

        // ===== P1: balanced projections (48 rows/warp, 2 batches) =====
        {
            const float4* Wp = first ? origA4 : fusedA4;
            float4 a0 = {0,0,0,0}, a1 = {0,0,0,0};
            #pragma unroll 8
            for (int i = 0; i < nA; ++i) {
                float4 wv4 = Wp[i * 32 + l];
                float x0 = sm[CUR + dA + i];
                float x1 = sm[CUR + DDIM + dA + i];
                a0.x += x0 * wv4.x; a0.y += x0 * wv4.y; a0.z += x0 * wv4.z; a0.w += x0 * wv4.w;
                a1.x += x1 * wv4.x; a1.y += x1 * wv4.y; a1.z += x1 * wv4.z; a1.w += x1 * wv4.w;
            }
            *(float4*)&sm[RED + (slotA * 2 + 0) * DDIM + (l << 2)] = a0;
            *(float4*)&sm[RED + (slotA * 2 + 1) * DDIM + (l << 2)] = a1;
            if (nB > 0) {
                const float4* Wp2 = first ? origB4 : fusedB4;
                float4 c0 = {0,0,0,0}, c1 = {0,0,0,0};
                #pragma unroll 8
                for (int i = 0; i < nB; ++i) {
                    float4 wv4 = Wp2[i * 32 + l];
                    float x0 = sm[CUR + i];
                    float x1 = sm[CUR + DDIM + i];
                    c0.x += x0 * wv4.x; c0.y += x0 * wv4.y; c0.z += x0 * wv4.z; c0.w += x0 * wv4.w;
                    c1.x += x1 * wv4.x; c1.y += x1 * wv4.y; c1.z += x1 * wv4.z; c1.w += x1 * wv4.w;
                }
                *(float4*)&sm[RED + (slotB * 2 + 0) * DDIM + (l << 2)] = c0;
                *(float4*)&sm[RED + (slotB * 2 + 1) * DDIM + (l << 2)] = c1;
            }
        }
        __syncthreads();

        // ===== P2: QK scores straight from partials (q inline, k[gen] inline) =====
        {
            // q = 0.125 * (slot0 + slot1 + slot2)   rows: b, 2+b, 4+b
            float4 qa = *(const float4*)&sm[RED + (0 + p2b) * DDIM + (l << 2)];
            float4 qb = *(const float4*)&sm[RED + (2 + p2b) * DDIM + (l << 2)];
            float4 qc = *(const float4*)&sm[RED + (4 + p2b) * DDIM + (l << 2)];
            float4 q4;
            q4.x = 0.125f * (qa.x + qb.x + qc.x);
            q4.y = 0.125f * (qa.y + qb.y + qc.y);
            q4.z = 0.125f * (qa.z + qb.z + qc.z);
            q4.w = 0.125f * (qa.w + qb.w + qc.w);

            const float4* kb4 = (const float4*)(kg + (size_t)p2b * BSTR) + l;
            #pragma unroll 8
            for (int r = 0; r < 16; ++r) {
                int s = p2s0 + r;
                float4 k4;
                if (s == gen) {      // warp-uniform: k[gen] = sum of k partial slots 3-6
                    float4 ka = *(const float4*)&sm[RED + (6 + p2b) * DDIM + (l << 2)];
                    float4 kb_ = *(const float4*)&sm[RED + (8 + p2b) * DDIM + (l << 2)];
                    float4 kc = *(const float4*)&sm[RED + (10 + p2b) * DDIM + (l << 2)];
                    float4 kd_ = *(const float4*)&sm[RED + (12 + p2b) * DDIM + (l << 2)];
                    k4.x = ka.x + kb_.x + kc.x + kd_.x;
                    k4.y = ka.y + kb_.y + kc.y + kd_.y;
                    k4.z = ka.z + kb_.z + kc.z + kd_.z;
                    k4.w = ka.w + kb_.w + kc.w + kd_.w;
                } else {
                    k4 = kb4[s * 32];
                }
                float p = k4.x * q4.x + k4.y * q4.y + k4.z * q4.z + k4.w * q4.w;
                #pragma unroll
                for (int o = 16; o > 0; o >>= 1) p += __shfl_xor_sync(0xFFFFFFFFu, p, o);
                if (l == 0) sm[ATT + p2b * SDIM + s] = p;
            }
        }
        __syncthreads();

        // ===== P4: softmax + cache writes (k/v[gen] inline) + AV -> cur =====
        {
            float s0 = sm[ATT + p4b * SDIM + l];
            float s1 = sm[ATT + p4b * SDIM + 32 + l];
            float mx = fmaxf(s0, s1);
            #pragma unroll
            for (int o = 16; o > 0; o >>= 1) mx = fmaxf(mx, __shfl_xor_sync(0xFFFFFFFFu, mx, o));
            float e0 = __expf(s0 - mx);
            float e1 = __expf(s1 - mx);
            float su = e0 + e1;
            #pragma unroll
            for (int o = 16; o > 0; o >>= 1) su += __shfl_xor_sync(0xFFFFFFFFu, su, o);
            float inv = 1.0f / su;
            float p0 = e0 * inv, p1 = e1 * inv;

            // inline k[gen][d], v[gen][d] from partials; write caches
            float kloc = sm[RED + (6 + p4b) * DDIM + p4d] + sm[RED + (8 + p4b) * DDIM + p4d]
                       + sm[RED + (10 + p4b) * DDIM + p4d] + sm[RED + (12 + p4b) * DDIM + p4d];
            float vloc = sm[RED + (14 + p4b) * DDIM + p4d] + sm[RED + (16 + p4b) * DDIM + p4d]
                       + sm[RED + (18 + p4b) * DDIM + p4d];
            kg[(size_t)p4b * BSTR + gen * DDIM + p4d] = kloc;
            vg[(size_t)p4b * BSTR + gen * DDIM + p4d] = vloc;
            sm[VS + (p4b * SDIM + gen) * DDIM + p4d] = vloc;   // column-exclusive, same-thread read below

            const float* vb = sm + VS + p4b * (SDIM * DDIM) + p4d;
            float acc = 0.f;
            #pragma unroll 8
            for (int s = 0; s < 32; ++s) {
                float a = __shfl_sync(0xFFFFFFFFu, p0, s);
                acc += a * vb[s * DDIM];
            }
            #pragma unroll 8
            for (int s = 0; s < 32; ++s) {
                float a = __shfl_sync(0xFFFFFFFFu, p1, s);
                acc += a * vb[(32 + s) * DDIM];
            }
            sm[CUR + p4b * DDIM + p4d] = acc;
        }
        __syncthreads();
    }

    // ---- epilogue: x_out = cur @ Wo ----
    const float4* Wo4 = (const float4*)(wo + (size_t)h * DDIM * DDIM);
    {
        float4 a0 = {0,0,0,0}, a1 = {0,0,0,0};
        const int d0 = w << 4;
        #pragma unroll 8
        for (int dd = 0; dd < 16; ++dd) {
            int d = d0 + dd;
            float4 wv4 = Wo4[d * 32 + l];
            float x0 = sm[CUR + d];
            float x1 = sm[CUR + DDIM + d];
            a0.x += x0 * wv4.x; a0.y += x0 * wv4.y; a0.z += x0 * wv4.z; a0.w += x0 * wv4.w;
            a1.x += x1 * wv4.x; a1.y += x1 * wv4.y; a1.z += x1 * wv4.z; a1.w += x1 * wv4.w;
        }
        *(float4*)&sm[RED + ((w << 1) + 0) * DDIM + (l << 2)] = a0;
        *(float4*)&sm[RED + ((w << 1) + 1) * DDIM + (l << 2)] = a1;
    }
    __syncthreads();
    {
        const int b = t >> 7, e = t & 127;
        float v = 0.f;
        #pragma unroll
        for (int ww = 0; ww < 8; ++ww)
            v += sm[RED + ((ww << 1) + b) * DDIM + e];
        x_out[(size_t)((b0 + b) * HDIM + h) * DDIM + e] = v;
    }
}

extern "C" void kernel_launch(void* const* d_in, const int* in_sizes, int n_in,
                              void* d_out, int out_size)
{
    const float* x  = (const float*)d_in[0];
    const float* k  = (const float*)d_in[1];
    const float* v  = (const float*)d_in[2];
    const float* wq = (const float*)d_in[3];
    const float* wk = (const float*)d_in[4];
    const float* wv = (const float*)d_in[5];
    const float* wo = (const float*)d_in[6];

    float* out   = (float*)d_out;
    float* k_out = out;
    float* v_out = out + (size_t)BDIM * HDIM * SDIM * DDIM;
    float* x_out = out + (size_t)2 * BDIM * HDIM * SDIM * DDIM;

    fuse_weights_kernel<<<HDIM * 12, 256>>>(wq, wk, wv, wo);

    size_t smem = SMEM_FLOATS * sizeof(float);
    cudaFuncSetAttribute(attn_decode_kernel,
                         cudaFuncAttributeMaxDynamicSharedMemorySize, (int)smem);
    attn_decode_kernel<<<BDIM * HDIM / 2, NT, smem>>>(
        x, k, v, wq, wk, wv, wo, k_out, v_out, x_out);
}

// round 11
// speedup vs baseline: 1.6877x; 1.6877x over previous
#include <cuda_runtime.h>

#define BDIM 128
#define HDIM 32
#define SDIM 64
#define DDIM 128
#define STARTLEN 32
#define NT 288                        // 9 warps: 3 per projection matrix
#define BSTR (HDIM * SDIM * DDIM)

// SMEM (floats): Vs[2][64][128]=16384, cur[2][128]=256, red[18][128]=2304, att[2][64]=128
// RED rows: q slots 0-2 (rows 0-5), k slots 3-5 (rows 6-11), v slots 6-8 (rows 12-17); row = slot*2+batch
#define VS   0
#define CUR  16384
#define RED  16640
#define ATT  (RED + 18 * DDIM)
#define SMEM_FLOATS 19072             // 76288 B -> 3 CTAs/SM

// Fused weights per head: [h][384][128]  (Wo@Wq | Wo@Wk | Wo@Wv)
__device__ float g_comb[HDIM * 3 * DDIM * DDIM];

// ---------------- fuse kernel: C = Wo @ Wm, 384 CTAs, 32-row panels ----------------
__global__ void __launch_bounds__(256)
fuse_weights_kernel(const float* __restrict__ wq, const float* __restrict__ wk,
                    const float* __restrict__ wv, const float* __restrict__ wo)
{
    __shared__ float Ws[DDIM * DDIM];
    __shared__ float Wop[32 * DDIM];
    const int h    = blockIdx.x / 12;
    const int rem  = blockIdx.x % 12;
    const int m    = rem >> 2;
    const int d0   = (rem & 3) << 5;
    const int t    = threadIdx.x;

    const float* Wm = ((m == 0) ? wq : ((m == 1) ? wk : wv)) + (size_t)h * DDIM * DDIM;
    const float* Wo = wo + (size_t)h * DDIM * DDIM;

    for (int i = t; i < DDIM * DDIM / 4; i += 256)
        ((float4*)Ws)[i] = ((const float4*)Wm)[i];
    for (int i = t; i < 32 * DDIM / 4; i += 256)
        ((float4*)Wop)[i] = ((const float4*)(Wo + d0 * DDIM))[i];
    __syncthreads();

    const int c = t & 15;
    const int r = t >> 4;
    float acc[2][8];
    #pragma unroll
    for (int i = 0; i < 2; ++i)
        #pragma unroll
        for (int j = 0; j < 8; ++j) acc[i][j] = 0.f;

    #pragma unroll 4
    for (int e = 0; e < DDIM; ++e) {
        float4 wm0 = *(const float4*)&Ws[e * DDIM + c * 8];
        float4 wm1 = *(const float4*)&Ws[e * DDIM + c * 8 + 4];
        #pragma unroll
        for (int i = 0; i < 2; ++i) {
            float wo_v = Wop[(r * 2 + i) * DDIM + e];
            acc[i][0] += wo_v * wm0.x; acc[i][1] += wo_v * wm0.y;
            acc[i][2] += wo_v * wm0.z; acc[i][3] += wo_v * wm0.w;
            acc[i][4] += wo_v * wm1.x; acc[i][5] += wo_v * wm1.y;
            acc[i][6] += wo_v * wm1.z; acc[i][7] += wo_v * wm1.w;
        }
    }

    float* dst = g_comb + ((size_t)h * 384 + m * DDIM + d0) * DDIM;
    #pragma unroll
    for (int i = 0; i < 2; ++i) {
        *(float4*)&dst[(r * 2 + i) * DDIM + c * 8]     = make_float4(acc[i][0], acc[i][1], acc[i][2], acc[i][3]);
        *(float4*)&dst[(r * 2 + i) * DDIM + c * 8 + 4] = make_float4(acc[i][4], acc[i][5], acc[i][6], acc[i][7]);
    }
}

// ---------------- decode kernel ----------------
__global__ void __launch_bounds__(NT, 3)
attn_decode_kernel(const float* __restrict__ x_in,
                   const float* __restrict__ k_in,
                   const float* __restrict__ v_in,
                   const float* __restrict__ wq,
                   const float* __restrict__ wk,
                   const float* __restrict__ wv,
                   const float* __restrict__ wo,
                   float* k_out, float* v_out, float* __restrict__ x_out)
{
    extern __shared__ float sm[];

    const int t = threadIdx.x;
    const int w = t >> 5;
    const int l = t & 31;
    const int h  = blockIdx.x >> 6;
    const int b0 = (blockIdx.x & 63) << 1;

    float* kg = k_out + (size_t)(b0 * HDIM + h) * (SDIM * DDIM);
    float* vg = v_out + (size_t)(b0 * HDIM + h) * (SDIM * DDIM);

    // ---- prologue: k_in -> k_out (global cache), v_in -> smem + v_out, x -> cur ----
    for (int b = 0; b < 2; ++b) {
        const float4* kin = (const float4*)(k_in + (size_t)((b0 + b) * HDIM + h) * (SDIM * DDIM));
        const float4* vin = (const float4*)(v_in + (size_t)((b0 + b) * HDIM + h) * (SDIM * DDIM));
        float4* kd = (float4*)(kg + (size_t)b * BSTR);
        float4* vd = (float4*)(vg + (size_t)b * BSTR);
        for (int i = t; i < SDIM * DDIM / 4; i += NT) {
            kd[i] = kin[i];
            float4 vv = vin[i];
            *(float4*)&sm[VS + b * 8192 + 4 * i] = vv;
            vd[i] = vv;
        }
        const float* xin = x_in + (size_t)((b0 + b) * HDIM + h) * DDIM;
        for (int d = t; d < DDIM; d += NT) sm[CUR + b * DDIM + d] = xin[d];
    }
    __syncthreads();

    // P1 clean split: matrix pm = w/3, segment ps = w%3, rows 43/43/42, slot = w
    const int pm = w / 3;
    const int ps = w - pm * 3;
    const int pd0 = (ps == 0) ? 0 : ((ps == 1) ? 43 : 86);
    const int pnR = (ps == 2) ? 42 : 43;

    const float* origM[3] = { wq + (size_t)h * DDIM * DDIM,
                              wk + (size_t)h * DDIM * DDIM,
                              wv + (size_t)h * DDIM * DDIM };
    const float* Ch = g_comb + (size_t)h * 384 * DDIM;

    const float4* orig4  = (const float4*)(origM[pm] + (size_t)pd0 * DDIM);
    const float4* fused4 = (const float4*)(Ch + (size_t)(pm * DDIM + pd0) * DDIM);

    const int p2b = w >> 2, p2s0 = (w & 3) << 4;     // P2 (w<8): (batch, s-quarter)
    const int p4b = t >> 7, p4d = t & 127;           // P4 (t<256): (batch, d)

    for (int gen = STARTLEN; gen < SDIM; ++gen) {
        const bool first = (gen == STARTLEN);

        // ===== P1: projections, 9 warps, one clean segment each =====
        {
            const float4* Wp = first ? orig4 : fused4;
            float4 a0 = {0,0,0,0}, a1 = {0,0,0,0};
            #pragma unroll 8
            for (int i = 0; i < pnR; ++i) {
                float4 wv4 = Wp[i * 32 + l];
                float x0 = sm[CUR + pd0 + i];
                float x1 = sm[CUR + DDIM + pd0 + i];
                a0.x += x0 * wv4.x; a0.y += x0 * wv4.y; a0.z += x0 * wv4.z; a0.w += x0 * wv4.w;
                a1.x += x1 * wv4.x; a1.y += x1 * wv4.y; a1.z += x1 * wv4.z; a1.w += x1 * wv4.w;
            }
            *(float4*)&sm[RED + ((w << 1) + 0) * DDIM + (l << 2)] = a0;
            *(float4*)&sm[RED + ((w << 1) + 1) * DDIM + (l << 2)] = a1;
        }
        __syncthreads();

        // ===== P2 (warps 0-7): QK scores straight from partials =====
        if (w < 8) {
            float4 qa = *(const float4*)&sm[RED + (0 + p2b) * DDIM + (l << 2)];
            float4 qb = *(const float4*)&sm[RED + (2 + p2b) * DDIM + (l << 2)];
            float4 qc = *(const float4*)&sm[RED + (4 + p2b) * DDIM + (l << 2)];
            float4 q4;
            q4.x = 0.125f * (qa.x + qb.x + qc.x);
            q4.y = 0.125f * (qa.y + qb.y + qc.y);
            q4.z = 0.125f * (qa.z + qb.z + qc.z);
            q4.w = 0.125f * (qa.w + qb.w + qc.w);

            const float4* kb4 = (const float4*)(kg + (size_t)p2b * BSTR) + l;
            #pragma unroll 8
            for (int r = 0; r < 16; ++r) {
                int s = p2s0 + r;
                float4 k4;
                if (s == gen) {      // warp-uniform: k[gen] = sum of k partial slots 3-5
                    float4 ka = *(const float4*)&sm[RED + (6 + p2b) * DDIM + (l << 2)];
                    float4 kb_ = *(const float4*)&sm[RED + (8 + p2b) * DDIM + (l << 2)];
                    float4 kc = *(const float4*)&sm[RED + (10 + p2b) * DDIM + (l << 2)];
                    k4.x = ka.x + kb_.x + kc.x;
                    k4.y = ka.y + kb_.y + kc.y;
                    k4.z = ka.z + kb_.z + kc.z;
                    k4.w = ka.w + kb_.w + kc.w;
                } else {
                    k4 = kb4[s * 32];
                }
                float p = k4.x * q4.x + k4.y * q4.y + k4.z * q4.z + k4.w * q4.w;
                #pragma unroll
                for (int o = 16; o > 0; o >>= 1) p += __shfl_xor_sync(0xFFFFFFFFu, p, o);
                if (l == 0) sm[ATT + p2b * SDIM + s] = p;
            }
        }
        __syncthreads();

        // ===== P4 (threads 0-255): softmax + cache writes + AV -> cur =====
        if (t < 256) {
            float s0 = sm[ATT + p4b * SDIM + l];
            float s1 = sm[ATT + p4b * SDIM + 32 + l];
            float mx = fmaxf(s0, s1);
            #pragma unroll
            for (int o = 16; o > 0; o >>= 1) mx = fmaxf(mx, __shfl_xor_sync(0xFFFFFFFFu, mx, o));
            float e0 = __expf(s0 - mx);
            float e1 = __expf(s1 - mx);
            float su = e0 + e1;
            #pragma unroll
            for (int o = 16; o > 0; o >>= 1) su += __shfl_xor_sync(0xFFFFFFFFu, su, o);
            float inv = 1.0f / su;
            float p0 = e0 * inv, p1 = e1 * inv;

            // inline k[gen][d], v[gen][d] from partials; write caches
            float kloc = sm[RED + (6 + p4b) * DDIM + p4d] + sm[RED + (8 + p4b) * DDIM + p4d]
                       + sm[RED + (10 + p4b) * DDIM + p4d];
            float vloc = sm[RED + (12 + p4b) * DDIM + p4d] + sm[RED + (14 + p4b) * DDIM + p4d]
                       + sm[RED + (16 + p4b) * DDIM + p4d];
            kg[(size_t)p4b * BSTR + gen * DDIM + p4d] = kloc;
            vg[(size_t)p4b * BSTR + gen * DDIM + p4d] = vloc;
            sm[VS + (p4b * SDIM + gen) * DDIM + p4d] = vloc;   // column-exclusive

            const float* vb = sm + VS + p4b * (SDIM * DDIM) + p4d;
            float acc = 0.f;
            #pragma unroll 8
            for (int s = 0; s < 32; ++s) {
                float a = __shfl_sync(0xFFFFFFFFu, p0, s);
                acc += a * vb[s * DDIM];
            }
            #pragma unroll 8
            for (int s = 0; s < 32; ++s) {
                float a = __shfl_sync(0xFFFFFFFFu, p1, s);
                acc += a * vb[(32 + s) * DDIM];
            }
            sm[CUR + p4b * DDIM + p4d] = acc;
        }
        __syncthreads();
    }

    // ---- epilogue: x_out = cur @ Wo ----
    const float4* Wo4 = (const float4*)(wo + (size_t)h * DDIM * DDIM);
    if (w < 8) {
        float4 a0 = {0,0,0,0}, a1 = {0,0,0,0};
        const int d0 = w << 4;
        #pragma unroll 8
        for (int dd = 0; dd < 16; ++dd) {
            int d = d0 + dd;
            float4 wv4 = Wo4[d * 32 + l];
            float x0 = sm[CUR + d];
            float x1 = sm[CUR + DDIM + d];
            a0.x += x0 * wv4.x; a0.y += x0 * wv4.y; a0.z += x0 * wv4.z; a0.w += x0 * wv4.w;
            a1.x += x1 * wv4.x; a1.y += x1 * wv4.y; a1.z += x1 * wv4.z; a1.w += x1 * wv4.w;
        }
        *(float4*)&sm[RED + ((w << 1) + 0) * DDIM + (l << 2)] = a0;
        *(float4*)&sm[RED + ((w << 1) + 1) * DDIM + (l << 2)] = a1;
    }
    __syncthreads();
    if (t < 256) {
        const int b = t >> 7, e = t & 127;
        float v = 0.f;
        #pragma unroll
        for (int ww = 0; ww < 8; ++ww)
            v += sm[RED + ((ww << 1) + b) * DDIM + e];
        x_out[(size_t)((b0 + b) * HDIM + h) * DDIM + e] = v;
    }
}

extern "C" void kernel_launch(void* const* d_in, const int* in_sizes, int n_in,
                              void* d_out, int out_size)
{
    const float* x  = (const float*)d_in[0];
    const float* k  = (const float*)d_in[1];
    const float* v  = (const float*)d_in[2];
    const float* wq = (const float*)d_in[3];
    const float* wk = (const float*)d_in[4];
    const float* wv = (const float*)d_in[5];
    const float* wo = (const float*)d_in[6];

    float* out   = (float*)d_out;
    float* k_out = out;
    float* v_out = out + (size_t)BDIM * HDIM * SDIM * DDIM;
    float* x_out = out + (size_t)2 * BDIM * HDIM * SDIM * DDIM;

    fuse_weights_kernel<<<HDIM * 12, 256>>>(wq, wk, wv, wo);

    size_t smem = SMEM_FLOATS * sizeof(float);
    cudaFuncSetAttribute(attn_decode_kernel,
                         cudaFuncAttributeMaxDynamicSharedMemorySize, (int)smem);
    attn_decode_kernel<<<BDIM * HDIM / 2, NT, smem>>>(
        x, k, v, wq, wk, wv, wo, k_out, v_out, x_out);
}

// round 12
// speedup vs baseline: 1.9016x; 1.1267x over previous
#include <cuda_runtime.h>

#define BDIM 128
#define HDIM 32
#define SDIM 64
#define DDIM 128
#define STARTLEN 32
#define NT 288                        // 9 warps: 3 per projection matrix, clean segments
#define BSTR (HDIM * SDIM * DDIM)

// SMEM (floats): Vs[2][64][128]=16384, cur[2][128]=256, red[18][128]=2304
// RED rows: slot s (=warp), batch b -> row 2s+b. q slots 0-2, k slots 3-5, v slots 6-8.
// After reduce: final q overlays rows 0-1; att overlays rows 2-3 (partials dead).
#define VS   0
#define CUR  16384
#define RED  16640
#define ATT  (RED + 2 * DDIM)
#define SMEM_FLOATS 18944             // 75776 B (+1KB driver = 76800) -> 3 CTAs/SM exactly

// Fused weights per head: [h][384][128]  (Wo@Wq | Wo@Wk | Wo@Wv)
__device__ float g_comb[HDIM * 3 * DDIM * DDIM];

// ---------------- fuse kernel: C = Wo @ Wm, 384 CTAs, 32-row panels ----------------
__global__ void __launch_bounds__(256)
fuse_weights_kernel(const float* __restrict__ wq, const float* __restrict__ wk,
                    const float* __restrict__ wv, const float* __restrict__ wo)
{
    __shared__ float Ws[DDIM * DDIM];
    __shared__ float Wop[32 * DDIM];
    const int h    = blockIdx.x / 12;
    const int rem  = blockIdx.x % 12;
    const int m    = rem >> 2;
    const int d0   = (rem & 3) << 5;
    const int t    = threadIdx.x;

    const float* Wm = ((m == 0) ? wq : ((m == 1) ? wk : wv)) + (size_t)h * DDIM * DDIM;
    const float* Wo = wo + (size_t)h * DDIM * DDIM;

    for (int i = t; i < DDIM * DDIM / 4; i += 256)
        ((float4*)Ws)[i] = ((const float4*)Wm)[i];
    for (int i = t; i < 32 * DDIM / 4; i += 256)
        ((float4*)Wop)[i] = ((const float4*)(Wo + d0 * DDIM))[i];
    __syncthreads();

    const int c = t & 15;
    const int r = t >> 4;
    float acc[2][8];
    #pragma unroll
    for (int i = 0; i < 2; ++i)
        #pragma unroll
        for (int j = 0; j < 8; ++j) acc[i][j] = 0.f;

    #pragma unroll 4
    for (int e = 0; e < DDIM; ++e) {
        float4 wm0 = *(const float4*)&Ws[e * DDIM + c * 8];
        float4 wm1 = *(const float4*)&Ws[e * DDIM + c * 8 + 4];
        #pragma unroll
        for (int i = 0; i < 2; ++i) {
            float wo_v = Wop[(r * 2 + i) * DDIM + e];
            acc[i][0] += wo_v * wm0.x; acc[i][1] += wo_v * wm0.y;
            acc[i][2] += wo_v * wm0.z; acc[i][3] += wo_v * wm0.w;
            acc[i][4] += wo_v * wm1.x; acc[i][5] += wo_v * wm1.y;
            acc[i][6] += wo_v * wm1.z; acc[i][7] += wo_v * wm1.w;
        }
    }

    float* dst = g_comb + ((size_t)h * 384 + m * DDIM + d0) * DDIM;
    #pragma unroll
    for (int i = 0; i < 2; ++i) {
        *(float4*)&dst[(r * 2 + i) * DDIM + c * 8]     = make_float4(acc[i][0], acc[i][1], acc[i][2], acc[i][3]);
        *(float4*)&dst[(r * 2 + i) * DDIM + c * 8 + 4] = make_float4(acc[i][4], acc[i][5], acc[i][6], acc[i][7]);
    }
}

// ---------------- decode kernel ----------------
__global__ void __launch_bounds__(NT, 3)
attn_decode_kernel(const float* __restrict__ x_in,
                   const float* __restrict__ k_in,
                   const float* __restrict__ v_in,
                   const float* __restrict__ wq,
                   const float* __restrict__ wk,
                   const float* __restrict__ wv,
                   const float* __restrict__ wo,
                   float* k_out, float* v_out, float* __restrict__ x_out)
{
    extern __shared__ float sm[];

    const int t = threadIdx.x;
    const int w = t >> 5;
    const int l = t & 31;
    const int h  = blockIdx.x >> 6;
    const int b0 = (blockIdx.x & 63) << 1;

    float* kg = k_out + (size_t)(b0 * HDIM + h) * (SDIM * DDIM);
    float* vg = v_out + (size_t)(b0 * HDIM + h) * (SDIM * DDIM);

    // ---- prologue: k_in -> k_out (global cache), v_in -> smem + v_out, x -> cur ----
    for (int b = 0; b < 2; ++b) {
        const float4* kin = (const float4*)(k_in + (size_t)((b0 + b) * HDIM + h) * (SDIM * DDIM));
        const float4* vin = (const float4*)(v_in + (size_t)((b0 + b) * HDIM + h) * (SDIM * DDIM));
        float4* kd = (float4*)(kg + (size_t)b * BSTR);
        float4* vd = (float4*)(vg + (size_t)b * BSTR);
        for (int i = t; i < SDIM * DDIM / 4; i += NT) {
            kd[i] = kin[i];
            float4 vv = vin[i];
            *(float4*)&sm[VS + b * 8192 + 4 * i] = vv;
            vd[i] = vv;
        }
        const float* xin = x_in + (size_t)((b0 + b) * HDIM + h) * DDIM;
        for (int d = t; d < DDIM; d += NT) sm[CUR + b * DDIM + d] = xin[d];
    }
    __syncthreads();

    // P1 clean split: matrix pm = w/3, segment ps = w%3; segments 44/44/40, 4-aligned
    const int pm  = w / 3;
    const int ps  = w - pm * 3;
    const int pd0 = ps * 44;
    const int pnR = (ps == 2) ? 40 : 44;

    const float* origM[3] = { wq + (size_t)h * DDIM * DDIM,
                              wk + (size_t)h * DDIM * DDIM,
                              wv + (size_t)h * DDIM * DDIM };
    const float* Ch = g_comb + (size_t)h * 384 * DDIM;

    const float4* orig4  = (const float4*)(origM[pm] + (size_t)pd0 * DDIM);
    const float4* fused4 = (const float4*)(Ch + (size_t)(pm * DDIM + pd0) * DDIM);

    const int p2b = w >> 2, p2s0 = (w & 3) << 4;     // P2 (w<8): (batch, s-quarter)
    const int p4b = t >> 7, p4d = t & 127;           // P4/reduce (t<256): (batch, d)

    for (int gen = STARTLEN; gen < SDIM; ++gen) {
        const bool first = (gen == STARTLEN);

        // ===== P1: projections, 9 warps, one clean 4-aligned segment each =====
        {
            const float4* Wp = first ? orig4 : fused4;
            float4 a0 = {0,0,0,0}, a1 = {0,0,0,0};
            #pragma unroll 8
            for (int i = 0; i < pnR; ++i) {
                float4 wv4 = Wp[i * 32 + l];
                float x0 = sm[CUR + pd0 + i];
                float x1 = sm[CUR + DDIM + pd0 + i];
                a0.x += x0 * wv4.x; a0.y += x0 * wv4.y; a0.z += x0 * wv4.z; a0.w += x0 * wv4.w;
                a1.x += x1 * wv4.x; a1.y += x1 * wv4.y; a1.z += x1 * wv4.z; a1.w += x1 * wv4.w;
            }
            *(float4*)&sm[RED + ((w << 1) + 0) * DDIM + (l << 2)] = a0;
            *(float4*)&sm[RED + ((w << 1) + 1) * DDIM + (l << 2)] = a1;
        }
        __syncthreads();

        // ===== reduce (t<256): q -> RED rows 0-1 (scaled); k[gen] -> kg; v[gen] -> Vs + vg =====
        if (t < 256) {
            const int b = p4b, e = p4d;
            float qv = sm[RED + (0 + b) * DDIM + e] + sm[RED + (2 + b) * DDIM + e]
                     + sm[RED + (4 + b) * DDIM + e];
            float kv = sm[RED + (6 + b) * DDIM + e] + sm[RED + (8 + b) * DDIM + e]
                     + sm[RED + (10 + b) * DDIM + e];
            float vv = sm[RED + (12 + b) * DDIM + e] + sm[RED + (14 + b) * DDIM + e]
                     + sm[RED + (16 + b) * DDIM + e];
            sm[RED + b * DDIM + e] = qv * 0.125f;             // final q (own column only)
            kg[(size_t)b * BSTR + gen * DDIM + e] = kv;
            sm[VS + (b * SDIM + gen) * DDIM + e] = vv;
            vg[(size_t)b * BSTR + gen * DDIM + e] = vv;
        }
        __syncthreads();

        // ===== P2 (w<8): QK scores from global K (full-unroll MLP) -> att rows 2-3 =====
        if (w < 8) {
            float4 q4 = *(const float4*)&sm[RED + p2b * DDIM + (l << 2)];
            const float4* kb4 = (const float4*)(kg + (size_t)p2b * BSTR) + l;
            #pragma unroll 16
            for (int r = 0; r < 16; ++r) {
                int s = p2s0 + r;
                float4 k4 = kb4[s * 32];
                float p = k4.x * q4.x + k4.y * q4.y + k4.z * q4.z + k4.w * q4.w;
                #pragma unroll
                for (int o = 16; o > 0; o >>= 1) p += __shfl_xor_sync(0xFFFFFFFFu, p, o);
                if (l == 0) sm[ATT + p2b * SDIM + s] = p;
            }
        }
        __syncthreads();

        // ===== P4 (t<256): per-warp register softmax + AV from smem V -> cur =====
        if (t < 256) {
            float s0 = sm[ATT + p4b * SDIM + l];
            float s1 = sm[ATT + p4b * SDIM + 32 + l];
            float mx = fmaxf(s0, s1);
            #pragma unroll
            for (int o = 16; o > 0; o >>= 1) mx = fmaxf(mx, __shfl_xor_sync(0xFFFFFFFFu, mx, o));
            float e0 = __expf(s0 - mx);
            float e1 = __expf(s1 - mx);
            float su = e0 + e1;
            #pragma unroll
            for (int o = 16; o > 0; o >>= 1) su += __shfl_xor_sync(0xFFFFFFFFu, su, o);
            float inv = 1.0f / su;
            float p0 = e0 * inv, p1 = e1 * inv;

            const float* vb = sm + VS + p4b * (SDIM * DDIM) + p4d;
            float acc = 0.f;
            #pragma unroll 8
            for (int s = 0; s < 32; ++s) {
                float a = __shfl_sync(0xFFFFFFFFu, p0, s);
                acc += a * vb[s * DDIM];
            }
            #pragma unroll 8
            for (int s = 0; s < 32; ++s) {
                float a = __shfl_sync(0xFFFFFFFFu, p1, s);
                acc += a * vb[(32 + s) * DDIM];
            }
            sm[CUR + p4b * DDIM + p4d] = acc;
        }
        __syncthreads();
    }

    // ---- epilogue: x_out = cur @ Wo ----
    const float4* Wo4 = (const float4*)(wo + (size_t)h * DDIM * DDIM);
    if (w < 8) {
        float4 a0 = {0,0,0,0}, a1 = {0,0,0,0};
        const int d0 = w << 4;
        #pragma unroll 8
        for (int dd = 0; dd < 16; ++dd) {
            int d = d0 + dd;
            float4 wv4 = Wo4[d * 32 + l];
            float x0 = sm[CUR + d];
            float x1 = sm[CUR + DDIM + d];
            a0.x += x0 * wv4.x; a0.y += x0 * wv4.y; a0.z += x0 * wv4.z; a0.w += x0 * wv4.w;
            a1.x += x1 * wv4.x; a1.y += x1 * wv4.y; a1.z += x1 * wv4.z; a1.w += x1 * wv4.w;
        }
        *(float4*)&sm[RED + ((w << 1) + 0) * DDIM + (l << 2)] = a0;
        *(float4*)&sm[RED + ((w << 1) + 1) * DDIM + (l << 2)] = a1;
    }
    __syncthreads();
    if (t < 256) {
        const int b = p4b, e = p4d;
        float v = 0.f;
        #pragma unroll
        for (int ww = 0; ww < 8; ++ww)
            v += sm[RED + ((ww << 1) + b) * DDIM + e];
        x_out[(size_t)((b0 + b) * HDIM + h) * DDIM + e] = v;
    }
}

extern "C" void kernel_launch(void* const* d_in, const int* in_sizes, int n_in,
                              void* d_out, int out_size)
{
    const float* x  = (const float*)d_in[0];
    const float* k  = (const float*)d_in[1];
    const float* v  = (const float*)d_in[2];
    const float* wq = (const float*)d_in[3];
    const float* wk = (const float*)d_in[4];
    const float* wv = (const float*)d_in[5];
    const float* wo = (const float*)d_in[6];

    float* out   = (float*)d_out;
    float* k_out = out;
    float* v_out = out + (size_t)BDIM * HDIM * SDIM * DDIM;
    float* x_out = out + (size_t)2 * BDIM * HDIM * SDIM * DDIM;

    fuse_weights_kernel<<<HDIM * 12, 256>>>(wq, wk, wv, wo);

    size_t smem = SMEM_FLOATS * sizeof(float);
    cudaFuncSetAttribute(attn_decode_kernel,
                         cudaFuncAttributeMaxDynamicSharedMemorySize, (int)smem);
    attn_decode_kernel<<<BDIM * HDIM / 2, NT, smem>>>(
        x, k, v, wq, wk, wv, wo, k_out, v_out, x_out);
}